// round 7
// baseline (speedup 1.0000x reference)
#include <cuda_runtime.h>
#include <math.h>

// Problem constants (match reference)
#define BB 8
#define HH 256
#define WW 256
#define RR 8                        // output rows per block
#define HALO 4                      // column window radius (exactness-checked)
#define DROWS (RR + 2 * HALO)       // decoded rows per block (16)
#define NBLK (BB * (HH / RR))       // 256 blocks

// ---------------------------------------------------------------------------
// Scratch (device globals — no allocation allowed)
// ---------------------------------------------------------------------------
__device__ double d_partials[NBLK][4];   // {sum p*dist, sum p*t, sum p*p, sum t*t}
__device__ int g_fin;                    // finalize election counter (self-resetting)

// Exact distance to nearest set (inv=false) / clear (inv=true) bit in a
// 256-bit row mask. Returns squared distance as float (1e10 if none == ref INF).
// Fallback-only.
__device__ __forceinline__ float exact_dist2(const unsigned* m, int i, bool inv) {
    const int wi = i >> 5, bi = i & 31;
    const unsigned mw = inv ? ~m[wi] : m[wi];
    const unsigned lowmask = (2u << bi) - 1u;
    const unsigned himask  = ~((1u << bi) - 1u);
    unsigned wl = mw & lowmask;
    int dl = 100000;
    if (wl) dl = bi - (31 - __clz(wl));
    else {
        for (int k = wi - 1; k >= 0; --k) {
            const unsigned mk = inv ? ~m[k] : m[k];
            if (mk) { dl = i - (k * 32 + 31 - __clz(mk)); break; }
        }
    }
    unsigned wr = mw & himask;
    int dr = 100000;
    if (wr) dr = (__ffs(wr) - 1) - bi;
    else {
        for (int k = wi + 1; k < 8; ++k) {
            const unsigned mk = inv ? ~m[k] : m[k];
            if (mk) { dr = (k * 32 + __ffs(mk) - 1) - i; break; }
        }
    }
    const int d = min(dl, dr);
    return (d >= 1000) ? 1e10f : (float)(d * d);
}

// ---------------------------------------------------------------------------
// Transposed fused kernel: thread = column, block = 8 output rows of one
// image. Ballot-built bit rows; per-pixel row-dist decode (clamped at 6);
// paired windowed column min-plus (K=4) with exactness check + exact
// fallback; fused sigmoid + dice/boundary partials; last-block finalize.
// ---------------------------------------------------------------------------
__global__ __launch_bounds__(WW) void fused(const float* __restrict__ pred,
                                            const float* __restrict__ target,
                                            const int* __restrict__ fl_ptr,
                                            float* __restrict__ out) {
    const int blk  = blockIdx.x;
    const int tid  = threadIdx.x;          // column x
    const int warp = tid >> 5;
    const int lane = tid & 31;

    const int b  = blk >> 5;               // image
    const int y0 = (blk & 31) * RR;        // first output row
    const int base = b * HH * WW;
    const int x = tid;

    __shared__ unsigned sbits[DROWS][8];   // decoded-row bit masks
    __shared__ unsigned sfull[HH][8];      // fallback-only: full-image bit rows
    __shared__ float rs[8][4];
    __shared__ double fg[8][2];
    __shared__ int s_last;

    // ---- Phase A: ballot-build DROWS bit rows (fully coalesced loads) ------
#pragma unroll
    for (int j = 0; j < DROWS; ++j) {
        const int rj = y0 - HALO + j;
        if (rj >= 0 && rj < HH) {
            const float t = target[base + rj * WW + (warp << 5) + lane];
            const unsigned bal = __ballot_sync(0xffffffffu, t > 0.5f);
            if (lane == 0) sbits[j][warp] = bal;
        }
    }
    __syncthreads();

    // ---- per-column window extraction setup --------------------------------
    const int sh  = x - 5;                 // window start bit (may be <0)
    const int wiw = sh >> 5;               // valid only when x >= 5
    const int shr = sh & 31;
    unsigned vm = 0x7FFu;
    if (x < 5)   vm &= (0x7FFu << (5 - x));
    if (x > 250) vm &= (0x7FFu >> (x - 250));

    float aa[RR], ab[RR];

    // ---- Pass 1: nearest-1 distances, then window min ----------------------
    {
        float da[DROWS];
#pragma unroll
        for (int j = 0; j < DROWS; ++j) {
            const int rj = y0 - HALO + j;
            if (rj >= 0 && rj < HH) {
                unsigned win;
                if (x >= 5) {
                    const unsigned lo = sbits[j][wiw];
                    const unsigned hi = (wiw < 7) ? sbits[j][wiw + 1] : 0u;
                    win = __funnelshift_r(lo, hi, shr) & 0x7FFu;
                } else {
                    win = (sbits[j][0] << (5 - x)) & 0x7FFu;
                }
                const unsigned wm = win & vm;
                const unsigned l5 = wm & 0x1Fu;
                const unsigned r5 = wm >> 6;
                const int dl = __clz(l5) - 26;            // l5==0 -> 6
                const int fr = __ffs(r5);
                const int dr = fr ? fr : 6;
                const int d  = ((wm >> 5) & 1u) ? 0 : min(dl, dr);
                da[j] = (float)(d * d);                   // 36 == clamped
            } else da[j] = 1e18f;
        }
#pragma unroll
        for (int i = 0; i < RR; ++i) {
            const float p1 = fminf(da[i + 3], da[i + 5]) + 1.0f;
            const float p2 = fminf(da[i + 2], da[i + 6]) + 4.0f;
            const float p3 = fminf(da[i + 1], da[i + 7]) + 9.0f;
            const float p4 = fminf(da[i],     da[i + 8]) + 16.0f;
            aa[i] = fminf(fminf(fminf(p1, p2), fminf(p3, p4)), da[i + 4]);
        }
    }
    // ---- Pass 2: nearest-0 distances, then window min ----------------------
    {
        float db[DROWS];
#pragma unroll
        for (int j = 0; j < DROWS; ++j) {
            const int rj = y0 - HALO + j;
            if (rj >= 0 && rj < HH) {
                unsigned win;
                if (x >= 5) {
                    const unsigned lo = sbits[j][wiw];
                    const unsigned hi = (wiw < 7) ? sbits[j][wiw + 1] : 0u;
                    win = __funnelshift_r(lo, hi, shr) & 0x7FFu;
                } else {
                    win = (sbits[j][0] << (5 - x)) & 0x7FFu;
                }
                const unsigned wm = (~win) & vm;
                const unsigned l5 = wm & 0x1Fu;
                const unsigned r5 = wm >> 6;
                const int dl = __clz(l5) - 26;
                const int fr = __ffs(r5);
                const int dr = fr ? fr : 6;
                const int d  = ((wm >> 5) & 1u) ? 0 : min(dl, dr);
                db[j] = (float)(d * d);
            } else db[j] = 1e18f;
        }
#pragma unroll
        for (int i = 0; i < RR; ++i) {
            const float p1 = fminf(db[i + 3], db[i + 5]) + 1.0f;
            const float p2 = fminf(db[i + 2], db[i + 6]) + 4.0f;
            const float p3 = fminf(db[i + 1], db[i + 7]) + 9.0f;
            const float p4 = fminf(db[i],     db[i + 8]) + 16.0f;
            ab[i] = fminf(fminf(fminf(p1, p2), fminf(p3, p4)), db[i + 4]);
        }
    }

    // ---- Exactness: fast result valid iff every windowed min <= 25 ---------
    float maxr = 0.0f;
#pragma unroll
    for (int i = 0; i < RR; ++i) maxr = fmaxf(maxr, fmaxf(aa[i], ab[i]));
    const int need_full = __syncthreads_or(maxr > 25.0f);
    if (need_full) {
        // Exact full-image fallback (deterministic; ~never executes).
        for (int r = 0; r < HH; ++r) {
            const float t = target[base + r * WW + (warp << 5) + lane];
            const unsigned bal = __ballot_sync(0xffffffffu, t > 0.5f);
            if (lane == 0) sfull[r][warp] = bal;
        }
        __syncthreads();
#pragma unroll
        for (int i = 0; i < RR; ++i) { aa[i] = 3.0e38f; ab[i] = 3.0e38f; }
        for (int r = 0; r < HH; ++r) {
            const float d1 = exact_dist2(sfull[r], x, false);
            const float d0 = exact_dist2(sfull[r], x, true);
#pragma unroll
            for (int i = 0; i < RR; ++i) {
                const float dy = (float)((y0 + i - r) * (y0 + i - r));
                aa[i] = fminf(aa[i], d1 + dy);
                ab[i] = fminf(ab[i], d0 + dy);
            }
        }
    }

    // ---- Epilogue: sigmoid + partial sums (coalesced pred; t from bits) ----
    const int fl = *fl_ptr;
    float s_pd = 0.0f, s_pt = 0.0f, s_pp = 0.0f;
    int s_tt = 0;
#pragma unroll
    for (int i = 0; i < RR; ++i) {
        float p = pred[base + (y0 + i) * WW + x];
        if (fl) p = __fdividef(1.0f, 1.0f + __expf(-p));
        const int t = (sbits[i + HALO][warp] >> lane) & 1u;
        const float dist = sqrtf(aa[i]) + sqrtf(ab[i]);
        s_pd += p * dist;
        s_pp += p * p;
        if (t) { s_pt += p; s_tt += 1; }
    }
    float s_ttf = (float)s_tt;

#pragma unroll
    for (int off = 16; off > 0; off >>= 1) {
        s_pd  += __shfl_down_sync(0xffffffffu, s_pd,  off);
        s_pt  += __shfl_down_sync(0xffffffffu, s_pt,  off);
        s_pp  += __shfl_down_sync(0xffffffffu, s_pp,  off);
        s_ttf += __shfl_down_sync(0xffffffffu, s_ttf, off);
    }
    if (lane == 0) {
        rs[warp][0] = s_pd; rs[warp][1] = s_pt;
        rs[warp][2] = s_pp; rs[warp][3] = s_ttf;
    }
    __syncthreads();

    if (tid == 0) {
        double a0 = 0.0, a1 = 0.0, a2 = 0.0, a3 = 0.0;
#pragma unroll
        for (int w = 0; w < 8; ++w) {
            a0 += (double)rs[w][0]; a1 += (double)rs[w][1];
            a2 += (double)rs[w][2]; a3 += (double)rs[w][3];
        }
        d_partials[blk][0] = a0; d_partials[blk][1] = a1;
        d_partials[blk][2] = a2; d_partials[blk][3] = a3;
        __threadfence();
        const int old = atomicAdd(&g_fin, 1);
        s_last = (old == NBLK - 1);
    }
    __syncthreads();
    if (!s_last) return;

    // ---- last block: deterministic finalize --------------------------------
    __threadfence();
    {
        const int g = warp;                // one warp per image (8 images)
        const int s = g * 32 + lane;       // 32 partials per image
        double v0 = d_partials[s][0];
        double v1 = d_partials[s][1];
        double v2 = d_partials[s][2];
        double v3 = d_partials[s][3];
#pragma unroll
        for (int off = 16; off > 0; off >>= 1) {
            v0 += __shfl_down_sync(0xffffffffu, v0, off);
            v1 += __shfl_down_sync(0xffffffffu, v1, off);
            v2 += __shfl_down_sync(0xffffffffu, v2, off);
            v3 += __shfl_down_sync(0xffffffffu, v3, off);
        }
        if (lane == 0) {
            const double eps = 1e-6;
            fg[g][0] = v0;                                        // boundary sum
            fg[g][1] = 1.0 - (2.0 * v1 + eps) / (v2 + v3 + eps);  // dice term
        }
    }
    __syncthreads();
    if (tid == 0) {
        double bl = 0.0, dl = 0.0;
#pragma unroll
        for (int g = 0; g < BB; ++g) { bl += fg[g][0]; dl += fg[g][1]; }
        dl /= (double)BB;
        bl /= (double)(BB * HH * WW);
        out[0] = (float)(dl + bl);  // ALPHA = BETA = 1
        g_fin = 0;                  // reset for next (graph) replay
        __threadfence();
    }
}

// ---------------------------------------------------------------------------
extern "C" void kernel_launch(void* const* d_in, const int* in_sizes, int n_in,
                              void* d_out, int out_size) {
    const float* pred   = (const float*)d_in[0];
    const float* target = (const float*)d_in[1];
    const int*   fl     = (const int*)d_in[2];
    float* out = (float*)d_out;

    fused<<<NBLK, WW>>>(pred, target, fl, out);
}

// round 8
// speedup vs baseline: 1.1067x; 1.1067x over previous
#include <cuda_runtime.h>
#include <math.h>

// Problem constants (match reference)
#define BB 8
#define HH 256
#define WW 256
#define RR 4                        // output rows per block
#define HALO 4                      // column window radius (exactness-checked)
#define DROWS (RR + 2 * HALO)       // decoded rows per block (12)
#define NBLK (BB * (HH / RR))       // 512 blocks

// ---------------------------------------------------------------------------
// Scratch (device globals — no allocation allowed)
// ---------------------------------------------------------------------------
__device__ double d_partials[NBLK][4];   // {sum p*dist, sum p*t, sum p*p, sum t*t}
__device__ int g_fin;                    // finalize election counter (self-resetting)

// Exact distance to nearest set (inv=false) / clear (inv=true) bit in a
// 256-bit row mask. Returns squared distance (1e10 if none == reference INF).
// Fallback-only.
__device__ __forceinline__ float exact_dist2(const unsigned* m, int i, bool inv) {
    const int wi = i >> 5, bi = i & 31;
    const unsigned mw = inv ? ~m[wi] : m[wi];
    const unsigned lowmask = (2u << bi) - 1u;
    const unsigned himask  = ~((1u << bi) - 1u);
    unsigned wl = mw & lowmask;
    int dl = 100000;
    if (wl) dl = bi - (31 - __clz(wl));
    else {
        for (int k = wi - 1; k >= 0; --k) {
            const unsigned mk = inv ? ~m[k] : m[k];
            if (mk) { dl = i - (k * 32 + 31 - __clz(mk)); break; }
        }
    }
    unsigned wr = mw & himask;
    int dr = 100000;
    if (wr) dr = (__ffs(wr) - 1) - bi;
    else {
        for (int k = wi + 1; k < 8; ++k) {
            const unsigned mk = inv ? ~m[k] : m[k];
            if (mk) { dr = (k * 32 + __ffs(mk) - 1) - i; break; }
        }
    }
    const int d = min(dl, dr);
    return (d >= 1000) ? 1e10f : (float)(d * d);
}

// ---------------------------------------------------------------------------
// Transposed fused kernel: thread = column, block = 4 output rows of one
// image (512 blocks). Hoisted pred loads; ballot-built bit rows; single
// window extraction feeding both masks; paired windowed min-plus (K=4) with
// exactness check + exact fallback; fused sigmoid + partials; last-block
// deterministic finalize.
// ---------------------------------------------------------------------------
__global__ __launch_bounds__(WW) void fused(const float* __restrict__ pred,
                                            const float* __restrict__ target,
                                            const int* __restrict__ fl_ptr,
                                            float* __restrict__ out) {
    const int blk  = blockIdx.x;
    const int tid  = threadIdx.x;          // column x
    const int warp = tid >> 5;
    const int lane = tid & 31;

    const int b  = blk >> 6;               // image  (64 blocks per image)
    const int y0 = (blk & 63) * RR;        // first output row
    const int base = b * HH * WW;
    const int x = tid;

    __shared__ unsigned sbits[DROWS][8];   // decoded-row bit masks
    __shared__ unsigned sfull[HH][8];      // fallback-only: full-image bit rows
    __shared__ float rs[8][4];
    __shared__ double fg[8][2];
    __shared__ int s_last;

    // ---- Hoisted global loads (overlap DRAM latency with everything) -------
    const int fl = *fl_ptr;
    float pv[RR];
#pragma unroll
    for (int i = 0; i < RR; ++i) pv[i] = pred[base + (y0 + i) * WW + x];

    // ---- Phase A: ballot-build DROWS bit rows (coalesced target reads) -----
#pragma unroll
    for (int j = 0; j < DROWS; ++j) {
        const int rj = y0 - HALO + j;
        if (rj >= 0 && rj < HH) {
            const float t = target[base + rj * WW + (warp << 5) + lane];
            const unsigned bal = __ballot_sync(0xffffffffu, t > 0.5f);
            if (lane == 0) sbits[j][warp] = bal;
        }
    }
    __syncthreads();

    // ---- per-column window extraction setup --------------------------------
    const int sh  = x - 5;                 // window start bit (may be <0)
    const int wiw = sh >> 5;               // valid only when x >= 5
    const int shr = sh & 31;
    unsigned vm = 0x7FFu;
    if (x < 5)   vm &= (0x7FFu << (5 - x));
    if (x > 250) vm &= (0x7FFu >> (x - 250));

    // ---- decode row distances (both masks from one window extraction) -----
    float da[DROWS], db[DROWS];
#pragma unroll
    for (int j = 0; j < DROWS; ++j) {
        const int rj = y0 - HALO + j;
        if (rj >= 0 && rj < HH) {
            unsigned win;
            if (x >= 5) {
                const unsigned lo = sbits[j][wiw];
                const unsigned hi = (wiw < 7) ? sbits[j][wiw + 1] : 0u;
                win = __funnelshift_r(lo, hi, shr) & 0x7FFu;
            } else {
                win = (sbits[j][0] << (5 - x)) & 0x7FFu;
            }
            // nearest 1
            unsigned wm = win & vm;
            unsigned l5 = wm & 0x1Fu, r5 = wm >> 6;
            int dl = __clz(l5) - 26;              // l5==0 -> 6
            int fr = __ffs(r5);
            int dr = fr ? fr : 6;
            int d  = ((wm >> 5) & 1u) ? 0 : min(dl, dr);
            da[j] = (float)(d * d);               // 36 == clamped (>=6)
            // nearest 0
            wm = (~win) & vm;
            l5 = wm & 0x1Fu; r5 = wm >> 6;
            dl = __clz(l5) - 26;
            fr = __ffs(r5);
            dr = fr ? fr : 6;
            d  = ((wm >> 5) & 1u) ? 0 : min(dl, dr);
            db[j] = (float)(d * d);
        } else { da[j] = 1e18f; db[j] = 1e18f; }
    }

    // ---- paired windowed column min-plus -----------------------------------
    float aa[RR], ab[RR];
#pragma unroll
    for (int i = 0; i < RR; ++i) {
        float p1 = fminf(da[i + 3], da[i + 5]) + 1.0f;
        float p2 = fminf(da[i + 2], da[i + 6]) + 4.0f;
        float p3 = fminf(da[i + 1], da[i + 7]) + 9.0f;
        float p4 = fminf(da[i],     da[i + 8]) + 16.0f;
        aa[i] = fminf(fminf(fminf(p1, p2), fminf(p3, p4)), da[i + 4]);
        p1 = fminf(db[i + 3], db[i + 5]) + 1.0f;
        p2 = fminf(db[i + 2], db[i + 6]) + 4.0f;
        p3 = fminf(db[i + 1], db[i + 7]) + 9.0f;
        p4 = fminf(db[i],     db[i + 8]) + 16.0f;
        ab[i] = fminf(fminf(fminf(p1, p2), fminf(p3, p4)), db[i + 4]);
    }

    // ---- Exactness: fast result valid iff every windowed min <= 25 ---------
    float maxr = 0.0f;
#pragma unroll
    for (int i = 0; i < RR; ++i) maxr = fmaxf(maxr, fmaxf(aa[i], ab[i]));
    const int need_full = __syncthreads_or(maxr > 25.0f);
    if (need_full) {
        // Exact full-image fallback (deterministic; ~never executes).
        for (int r = 0; r < HH; ++r) {
            const float t = target[base + r * WW + (warp << 5) + lane];
            const unsigned bal = __ballot_sync(0xffffffffu, t > 0.5f);
            if (lane == 0) sfull[r][warp] = bal;
        }
        __syncthreads();
#pragma unroll
        for (int i = 0; i < RR; ++i) { aa[i] = 3.0e38f; ab[i] = 3.0e38f; }
        for (int r = 0; r < HH; ++r) {
            const float d1 = exact_dist2(sfull[r], x, false);
            const float d0 = exact_dist2(sfull[r], x, true);
#pragma unroll
            for (int i = 0; i < RR; ++i) {
                const float dy = (float)((y0 + i - r) * (y0 + i - r));
                aa[i] = fminf(aa[i], d1 + dy);
                ab[i] = fminf(ab[i], d0 + dy);
            }
        }
    }

    // ---- Epilogue: sigmoid + partial sums (pred preloaded; t from bits) ----
    float s_pd = 0.0f, s_pt = 0.0f, s_pp = 0.0f;
    int s_tt = 0;
#pragma unroll
    for (int i = 0; i < RR; ++i) {
        float p = pv[i];
        if (fl) p = __fdividef(1.0f, 1.0f + __expf(-p));
        const int t = (sbits[i + HALO][warp] >> lane) & 1u;
        const float dist = sqrtf(aa[i]) + sqrtf(ab[i]);
        s_pd += p * dist;
        s_pp += p * p;
        if (t) { s_pt += p; s_tt += 1; }
    }
    float s_ttf = (float)s_tt;

#pragma unroll
    for (int off = 16; off > 0; off >>= 1) {
        s_pd  += __shfl_down_sync(0xffffffffu, s_pd,  off);
        s_pt  += __shfl_down_sync(0xffffffffu, s_pt,  off);
        s_pp  += __shfl_down_sync(0xffffffffu, s_pp,  off);
        s_ttf += __shfl_down_sync(0xffffffffu, s_ttf, off);
    }
    if (lane == 0) {
        rs[warp][0] = s_pd; rs[warp][1] = s_pt;
        rs[warp][2] = s_pp; rs[warp][3] = s_ttf;
    }
    __syncthreads();

    if (tid == 0) {
        double a0 = 0.0, a1 = 0.0, a2 = 0.0, a3 = 0.0;
#pragma unroll
        for (int w = 0; w < 8; ++w) {
            a0 += (double)rs[w][0]; a1 += (double)rs[w][1];
            a2 += (double)rs[w][2]; a3 += (double)rs[w][3];
        }
        d_partials[blk][0] = a0; d_partials[blk][1] = a1;
        d_partials[blk][2] = a2; d_partials[blk][3] = a3;
        __threadfence();
        const int old = atomicAdd(&g_fin, 1);
        s_last = (old == NBLK - 1);
    }
    __syncthreads();
    if (!s_last) return;

    // ---- last block: deterministic finalize --------------------------------
    __threadfence();
    {
        const int g = warp;                // one warp per image (8 images)
        const int s = g * 64 + lane;       // 64 partials per image
        double v0 = d_partials[s][0] + d_partials[s + 32][0];
        double v1 = d_partials[s][1] + d_partials[s + 32][1];
        double v2 = d_partials[s][2] + d_partials[s + 32][2];
        double v3 = d_partials[s][3] + d_partials[s + 32][3];
#pragma unroll
        for (int off = 16; off > 0; off >>= 1) {
            v0 += __shfl_down_sync(0xffffffffu, v0, off);
            v1 += __shfl_down_sync(0xffffffffu, v1, off);
            v2 += __shfl_down_sync(0xffffffffu, v2, off);
            v3 += __shfl_down_sync(0xffffffffu, v3, off);
        }
        if (lane == 0) {
            const double eps = 1e-6;
            fg[g][0] = v0;                                        // boundary sum
            fg[g][1] = 1.0 - (2.0 * v1 + eps) / (v2 + v3 + eps);  // dice term
        }
    }
    __syncthreads();
    if (tid == 0) {
        double bl = 0.0, dl = 0.0;
#pragma unroll
        for (int g = 0; g < BB; ++g) { bl += fg[g][0]; dl += fg[g][1]; }
        dl /= (double)BB;
        bl /= (double)(BB * HH * WW);
        out[0] = (float)(dl + bl);  // ALPHA = BETA = 1
        g_fin = 0;                  // reset for next (graph) replay
        __threadfence();
    }
}

// ---------------------------------------------------------------------------
extern "C" void kernel_launch(void* const* d_in, const int* in_sizes, int n_in,
                              void* d_out, int out_size) {
    const float* pred   = (const float*)d_in[0];
    const float* target = (const float*)d_in[1];
    const int*   fl     = (const int*)d_in[2];
    float* out = (float*)d_out;

    fused<<<NBLK, WW>>>(pred, target, fl, out);
}